// round 12
// baseline (speedup 1.0000x reference)
#include <cuda_runtime.h>
#include <cstdint>

#define BQ   2
#define NCAM 6
#define CCH  256
#define MQ   900
#define NLVL 4
#define EPSV 1e-5f

__constant__ int c_H[NLVL]  = {116, 58, 29, 15};
__constant__ int c_W[NLVL]  = {200, 100, 50, 25};
__constant__ int c_HW[NLVL] = {23200, 5800, 1450, 375};

#define NENT  (NCAM * NLVL)   // 24 real entries
#define DUMMY NENT            // slot 24 = zero-weight dummy

// one 16B record per (entry, corner): single LDS.128 in phase 2
struct __align__(16) Ent {
    const float* p;   // feature base + corner offset
    float w;          // bilinear weight for this corner
    int   hw;         // channel stride (H*W); 0 for dummy
};

__global__ __launch_bounds__(CCH, 6)
void FeatureSampler_kernel(const float* __restrict__ f0,
                           const float* __restrict__ f1,
                           const float* __restrict__ f2,
                           const float* __restrict__ f3,
                           const float* __restrict__ refpts,
                           const float* __restrict__ l2i,
                           float* __restrict__ out)
{
    const int bm  = blockIdx.x;          // b * MQ + m
    const int b   = bm / MQ;
    const int L   = threadIdx.x & 31;    // lane
    const int wrp = threadIdx.x >> 5;    // warp 0..7

    // corner in low 2 lane bits: lanes 0/1 (x0,x1 row y0) coalesce into one
    // 32B sector; lanes 2/3 likewise for row y1.
    const int corner = L & 3;
    const int chsub  = wrp * 8 + (L >> 2);   // channel sub-index 0..63

    __shared__ Ent   s_ent[(NENT + 1) * 4];  // (entry*4 + corner)
    __shared__ int   s_list[NENT + 2];       // padded to even
    __shared__ int   s_ne;
    __shared__ float s_cnt;

    // ---- Phase 1 (warp 0 only): build entries + ballot compaction ----
    if (wrp == 0) {
        const int t   = L;               // entry index (t<24 real, 24..27 dummy init)
        const int n   = t >> 2;          // camera
        const int lvl = t & 3;           // level

        int  active = 0;
        bool vcam   = false;

        if (t < NENT) {
            const float* rp = refpts + (size_t)bm * 3;
            float rx = rp[0] * 122.4f - 61.2f;
            float ry = rp[1] * 122.4f - 61.2f;
            float rz = rp[2] * 20.0f  - 10.0f;

            const float* Mt = l2i + (size_t)(b * NCAM + n) * 16;
            float cx = Mt[0]*rx + Mt[1]*ry + Mt[2] *rz + Mt[3];
            float cy = Mt[4]*rx + Mt[5]*ry + Mt[6] *rz + Mt[7];
            float cz = Mt[8]*rx + Mt[9]*ry + Mt[10]*rz + Mt[11];

            vcam = (cz > EPSV);

            float inv = 1.0f / (cz + EPSV);
            float x = cx * inv - 0.5f;   // grid_sample denorm cancels across levels
            float y = cy * inv - 0.5f;

            const int W  = c_W[lvl];
            const int H  = c_H[lvl];
            const int HW = c_HW[lvl];

            if (vcam && (x > -1.0f) && (x < (float)W) && (y > -1.0f) && (y < (float)H)) {
                float x0f = floorf(x), y0f = floorf(y);
                float wx1 = x - x0f, wx0 = 1.0f - wx1;
                float wy1 = y - y0f, wy0 = 1.0f - wy1;

                bool vx0 = (x0f >= 0.0f)        && (x0f <= (float)(W - 1));
                bool vx1 = (x0f + 1.0f >= 0.0f) && (x0f + 1.0f <= (float)(W - 1));
                bool vy0 = (y0f >= 0.0f)        && (y0f <= (float)(H - 1));
                bool vy1 = (y0f + 1.0f >= 0.0f) && (y0f + 1.0f <= (float)(H - 1));

                int xi0 = (int)fminf(fmaxf(x0f,        0.0f), (float)(W - 1));
                int xi1 = (int)fminf(fmaxf(x0f + 1.0f, 0.0f), (float)(W - 1));
                int yi0 = (int)fminf(fmaxf(y0f,        0.0f), (float)(H - 1));
                int yi1 = (int)fminf(fmaxf(y0f + 1.0f, 0.0f), (float)(H - 1));

                float w00 = (vx0 && vy0) ? (wx0 * wy0) : 0.0f;
                float w01 = (vx1 && vy0) ? (wx1 * wy0) : 0.0f;
                float w10 = (vx0 && vy1) ? (wx0 * wy1) : 0.0f;
                float w11 = (vx1 && vy1) ? (wx1 * wy1) : 0.0f;

                if ((w00 != 0.0f) || (w01 != 0.0f) || (w10 != 0.0f) || (w11 != 0.0f)) {
                    active = 1;
                    const float* fl = (lvl == 0) ? f0 : (lvl == 1) ? f1 :
                                      (lvl == 2) ? f2 : f3;
                    const float* base = fl + (size_t)(b * NCAM + n) * CCH * HW;
                    Ent e0 = { base + (yi0 * W + xi0), w00, HW };
                    Ent e1 = { base + (yi0 * W + xi1), w01, HW };
                    Ent e2 = { base + (yi1 * W + xi0), w10, HW };
                    Ent e3 = { base + (yi1 * W + xi1), w11, HW };
                    s_ent[t*4 + 0] = e0;
                    s_ent[t*4 + 1] = e1;
                    s_ent[t*4 + 2] = e2;
                    s_ent[t*4 + 3] = e3;
                }
            }
        } else if (t < NENT + 4) {
            // dummy slot: w=0, hw=0 -> broadcast load of f0[0], contributes 0
            Ent ed = { f0, 0.0f, 0 };
            s_ent[DUMMY*4 + (t - NENT)] = ed;
        }

        // ballot compaction
        unsigned amask = __ballot_sync(0xFFFFFFFFu, active != 0);
        if (active) {
            int pos = __popc(amask & ((1u << t) - 1u));
            s_list[pos] = t;
        }
        unsigned vmask = __ballot_sync(0xFFFFFFFFu, vcam && (lvl == 0) && (t < NENT));
        if (L == 0) {
            int ne = __popc(amask);
            if (ne & 1) s_list[ne] = DUMMY;   // pad to even
            s_ne  = (ne + 1) & ~1;
            s_cnt = (float)__popc(vmask);
        }
    }
    __syncthreads();

    const int   ne2 = s_ne;
    const float cnt = s_cnt;

    // ---- Phase 2: uniform x2-unrolled gather; one LDS.128 per entry ----
    float acc0 = 0.0f, acc1 = 0.0f, acc2 = 0.0f, acc3 = 0.0f;

    for (int k = 0; k < ne2; k += 2) {
        const int ea = s_list[k];
        const int eb = s_list[k + 1];
        const Ent Ea = s_ent[ea*4 + corner];   // LDS.128
        const Ent Eb = s_ent[eb*4 + corner];   // LDS.128

        const float* pa = Ea.p + (size_t)chsub * Ea.hw;
        const float* pb = Eb.p + (size_t)chsub * Eb.hw;

        float a0 = __ldg(pa);
        float a1 = __ldg(pa + (size_t)64  * Ea.hw);
        float a2 = __ldg(pa + (size_t)128 * Ea.hw);
        float a3 = __ldg(pa + (size_t)192 * Ea.hw);
        float b0 = __ldg(pb);
        float b1 = __ldg(pb + (size_t)64  * Eb.hw);
        float b2 = __ldg(pb + (size_t)128 * Eb.hw);
        float b3 = __ldg(pb + (size_t)192 * Eb.hw);

        acc0 += a0 * Ea.w;  acc1 += a1 * Ea.w;
        acc2 += a2 * Ea.w;  acc3 += a3 * Ea.w;
        acc0 += b0 * Eb.w;  acc1 += b1 * Eb.w;
        acc2 += b2 * Eb.w;  acc3 += b3 * Eb.w;
    }

    // single quad butterfly at the end (sum the 4 corners)
    acc0 += __shfl_xor_sync(0xFFFFFFFFu, acc0, 1);
    acc1 += __shfl_xor_sync(0xFFFFFFFFu, acc1, 1);
    acc2 += __shfl_xor_sync(0xFFFFFFFFu, acc2, 1);
    acc3 += __shfl_xor_sync(0xFFFFFFFFu, acc3, 1);
    acc0 += __shfl_xor_sync(0xFFFFFFFFu, acc0, 2);
    acc1 += __shfl_xor_sync(0xFFFFFFFFu, acc1, 2);
    acc2 += __shfl_xor_sync(0xFFFFFFFFu, acc2, 2);
    acc3 += __shfl_xor_sync(0xFFFFFFFFu, acc3, 2);

    if (corner == 0) {
        const float s = 0.25f / (cnt + EPSV);
        float* o = out + (size_t)bm * CCH + chsub;
        o[0]   = acc0 * s;
        o[64]  = acc1 * s;
        o[128] = acc2 * s;
        o[192] = acc3 * s;
    }
}

extern "C" void kernel_launch(void* const* d_in, const int* in_sizes, int n_in,
                              void* d_out, int out_size)
{
    const float* f0  = (const float*)d_in[0];
    const float* f1  = (const float*)d_in[1];
    const float* f2  = (const float*)d_in[2];
    const float* f3  = (const float*)d_in[3];
    const float* rp  = (const float*)d_in[4];
    const float* l2i = (const float*)d_in[5];
    float* out = (float*)d_out;

    dim3 grid(BQ * MQ);
    dim3 block(CCH);
    FeatureSampler_kernel<<<grid, block>>>(f0, f1, f2, f3, rp, l2i, out);
}

// round 15
// speedup vs baseline: 1.0102x; 1.0102x over previous
#include <cuda_runtime.h>
#include <cstdint>

#define BQ   2
#define NCAM 6
#define CCH  256
#define MQ   900
#define NLVL 4
#define EPSV 1e-5f

__constant__ int c_H[NLVL]  = {116, 58, 29, 15};
__constant__ int c_W[NLVL]  = {200, 100, 50, 25};
__constant__ int c_HW[NLVL] = {23200, 5800, 1450, 375};

#define NENT  (NCAM * NLVL)   // 24

// 16B record per (entry, corner): {base pointer, weight, channel stride}
struct __align__(16) Ent {
    const float* p;   // feature base + corner offset (corner-specific)
    float w;          // bilinear weight for this corner
    int   hw;         // channel stride H*W
};

__global__ __launch_bounds__(CCH, 8)
void FeatureSampler_kernel(const float* __restrict__ f0,
                           const float* __restrict__ f1,
                           const float* __restrict__ f2,
                           const float* __restrict__ f3,
                           const float* __restrict__ refpts,
                           const float* __restrict__ l2i,
                           float* __restrict__ out)
{
    const int bm  = blockIdx.x;          // b * MQ + m
    const int b   = bm / MQ;
    const int L   = threadIdx.x & 31;    // lane
    const int wrp = threadIdx.x >> 5;    // warp 0..7

    // corner in low 2 lane bits: lanes 0/1 (x0,x1 of row y0) coalesce into one
    // 32B sector; lanes 2/3 likewise for row y1.
    const int corner = L & 3;
    const int chsub  = wrp * 8 + (L >> 2);   // channel sub-index 0..63

    __shared__ Ent   s_ent[NENT * 4];        // (entry*4 + corner)
    __shared__ int   s_list[NENT];
    __shared__ int   s_ne;
    __shared__ float s_cnt;

    // ---- Phase 1 (warp 0 only): build entries + ballot compaction ----
    if (wrp == 0) {
        const int t   = L;               // entry index (t<24 meaningful)
        const int n   = t >> 2;          // camera
        const int lvl = t & 3;           // level

        int  active = 0;
        bool vcam   = false;

        if (t < NENT) {
            const float* rp = refpts + (size_t)bm * 3;
            float rx = rp[0] * 122.4f - 61.2f;
            float ry = rp[1] * 122.4f - 61.2f;
            float rz = rp[2] * 20.0f  - 10.0f;

            const float* Mt = l2i + (size_t)(b * NCAM + n) * 16;
            float cx = Mt[0]*rx + Mt[1]*ry + Mt[2] *rz + Mt[3];
            float cy = Mt[4]*rx + Mt[5]*ry + Mt[6] *rz + Mt[7];
            float cz = Mt[8]*rx + Mt[9]*ry + Mt[10]*rz + Mt[11];

            vcam = (cz > EPSV);

            float inv = 1.0f / (cz + EPSV);
            float x = cx * inv - 0.5f;   // grid_sample denorm cancels across levels
            float y = cy * inv - 0.5f;

            const int W  = c_W[lvl];
            const int H  = c_H[lvl];
            const int HW = c_HW[lvl];

            if (vcam && (x > -1.0f) && (x < (float)W) && (y > -1.0f) && (y < (float)H)) {
                float x0f = floorf(x), y0f = floorf(y);
                float wx1 = x - x0f, wx0 = 1.0f - wx1;
                float wy1 = y - y0f, wy0 = 1.0f - wy1;

                bool vx0 = (x0f >= 0.0f)        && (x0f <= (float)(W - 1));
                bool vx1 = (x0f + 1.0f >= 0.0f) && (x0f + 1.0f <= (float)(W - 1));
                bool vy0 = (y0f >= 0.0f)        && (y0f <= (float)(H - 1));
                bool vy1 = (y0f + 1.0f >= 0.0f) && (y0f + 1.0f <= (float)(H - 1));

                int xi0 = (int)fminf(fmaxf(x0f,        0.0f), (float)(W - 1));
                int xi1 = (int)fminf(fmaxf(x0f + 1.0f, 0.0f), (float)(W - 1));
                int yi0 = (int)fminf(fmaxf(y0f,        0.0f), (float)(H - 1));
                int yi1 = (int)fminf(fmaxf(y0f + 1.0f, 0.0f), (float)(H - 1));

                float w00 = (vx0 && vy0) ? (wx0 * wy0) : 0.0f;
                float w01 = (vx1 && vy0) ? (wx1 * wy0) : 0.0f;
                float w10 = (vx0 && vy1) ? (wx0 * wy1) : 0.0f;
                float w11 = (vx1 && vy1) ? (wx1 * wy1) : 0.0f;

                if ((w00 != 0.0f) || (w01 != 0.0f) || (w10 != 0.0f) || (w11 != 0.0f)) {
                    active = 1;
                    const float* fl = (lvl == 0) ? f0 : (lvl == 1) ? f1 :
                                      (lvl == 2) ? f2 : f3;
                    const float* base = fl + (size_t)(b * NCAM + n) * CCH * HW;
                    Ent e0 = { base + (yi0 * W + xi0), w00, HW };
                    Ent e1 = { base + (yi0 * W + xi1), w01, HW };
                    Ent e2 = { base + (yi1 * W + xi0), w10, HW };
                    Ent e3 = { base + (yi1 * W + xi1), w11, HW };
                    s_ent[t*4 + 0] = e0;
                    s_ent[t*4 + 1] = e1;
                    s_ent[t*4 + 2] = e2;
                    s_ent[t*4 + 3] = e3;
                }
            }
        }

        unsigned amask = __ballot_sync(0xFFFFFFFFu, active != 0);
        if (active) {
            int pos = __popc(amask & ((1u << t) - 1u));
            s_list[pos] = t;
        }
        unsigned vmask = __ballot_sync(0xFFFFFFFFu, vcam && (lvl == 0) && (t < NENT));
        if (L == 0) {
            s_ne  = __popc(amask);
            s_cnt = (float)__popc(vmask);
        }
    }
    __syncthreads();

    const int   ne  = s_ne;
    const float cnt = s_cnt;

    // ---- Phase 2: x2-unrolled gather, 32-bit offset math to keep regs low ----
    float acc0 = 0.0f, acc1 = 0.0f, acc2 = 0.0f, acc3 = 0.0f;

    int k = 0;
    for (; k + 1 < ne; k += 2) {
        const Ent Ea = s_ent[s_list[k]     * 4 + corner];   // LDS.128
        const Ent Eb = s_ent[s_list[k + 1] * 4 + corner];   // LDS.128

        const int sa = Ea.hw;           // channel stride
        const int sb = Eb.hw;
        const int oa = chsub * sa;      // fits in int (max ~1.5M)
        const int ob = chsub * sb;
        const int sa64 = sa * 64;       // 64-channel step (max ~1.5M)
        const int sb64 = sb * 64;

        const float* pa = Ea.p + oa;
        const float* pb = Eb.p + ob;

        float a0 = __ldg(pa);
        float a1 = __ldg(pa + sa64);
        float a2 = __ldg(pa + sa64 * 2);
        float a3 = __ldg(pa + sa64 * 3);
        float b0 = __ldg(pb);
        float b1 = __ldg(pb + sb64);
        float b2 = __ldg(pb + sb64 * 2);
        float b3 = __ldg(pb + sb64 * 3);

        acc0 += a0 * Ea.w;  acc1 += a1 * Ea.w;
        acc2 += a2 * Ea.w;  acc3 += a3 * Ea.w;
        acc0 += b0 * Eb.w;  acc1 += b1 * Eb.w;
        acc2 += b2 * Eb.w;  acc3 += b3 * Eb.w;
    }
    if (k < ne) {
        const Ent Ea = s_ent[s_list[k] * 4 + corner];
        const int sa = Ea.hw;
        const int sa64 = sa * 64;
        const float* pa = Ea.p + chsub * sa;
        acc0 += __ldg(pa)            * Ea.w;
        acc1 += __ldg(pa + sa64)     * Ea.w;
        acc2 += __ldg(pa + sa64 * 2) * Ea.w;
        acc3 += __ldg(pa + sa64 * 3) * Ea.w;
    }

    // single quad butterfly at the end (sum the 4 corners)
    acc0 += __shfl_xor_sync(0xFFFFFFFFu, acc0, 1);
    acc1 += __shfl_xor_sync(0xFFFFFFFFu, acc1, 1);
    acc2 += __shfl_xor_sync(0xFFFFFFFFu, acc2, 1);
    acc3 += __shfl_xor_sync(0xFFFFFFFFu, acc3, 1);
    acc0 += __shfl_xor_sync(0xFFFFFFFFu, acc0, 2);
    acc1 += __shfl_xor_sync(0xFFFFFFFFu, acc1, 2);
    acc2 += __shfl_xor_sync(0xFFFFFFFFu, acc2, 2);
    acc3 += __shfl_xor_sync(0xFFFFFFFFu, acc3, 2);

    if (corner == 0) {
        const float s = 0.25f / (cnt + EPSV);
        float* o = out + (size_t)bm * CCH + chsub;
        o[0]   = acc0 * s;
        o[64]  = acc1 * s;
        o[128] = acc2 * s;
        o[192] = acc3 * s;
    }
}

extern "C" void kernel_launch(void* const* d_in, const int* in_sizes, int n_in,
                              void* d_out, int out_size)
{
    const float* f0  = (const float*)d_in[0];
    const float* f1  = (const float*)d_in[1];
    const float* f2  = (const float*)d_in[2];
    const float* f3  = (const float*)d_in[3];
    const float* rp  = (const float*)d_in[4];
    const float* l2i = (const float*)d_in[5];
    float* out = (float*)d_out;

    dim3 grid(BQ * MQ);
    dim3 block(CCH);
    FeatureSampler_kernel<<<grid, block>>>(f0, f1, f2, f3, rp, l2i, out);
}

// round 16
// speedup vs baseline: 1.1562x; 1.1445x over previous
#include <cuda_runtime.h>
#include <cstdint>

#define BQ   2
#define NCAM 6
#define CCH  256
#define MQ   900
#define NLVL 4
#define EPSV 1e-5f

__constant__ int c_H[NLVL]  = {116, 58, 29, 15};
__constant__ int c_W[NLVL]  = {200, 100, 50, 25};
__constant__ int c_HW[NLVL] = {23200, 5800, 1450, 375};

#define NENT (NCAM * NLVL)   // 24

__global__ __launch_bounds__(128, 12)
void FeatureSampler_kernel(const float* __restrict__ f0,
                           const float* __restrict__ f1,
                           const float* __restrict__ f2,
                           const float* __restrict__ f3,
                           const float* __restrict__ refpts,
                           const float* __restrict__ l2i,
                           float* __restrict__ out)
{
    const int bm   = blockIdx.x;         // b * MQ + m
    const int half = blockIdx.y;         // which 32-channel-sub half
    const int b    = bm / MQ;
    const int L    = threadIdx.x & 31;   // lane
    const int wrp  = threadIdx.x >> 5;   // warp 0..3

    // corner in low 2 lane bits: lanes 0/1 (x0,x1 row y0) coalesce into one
    // 32B sector; lanes 2/3 likewise for row y1.
    const int corner = L & 3;
    const int chsub  = half * 32 + wrp * 8 + (L >> 2);   // 0..63 across both halves

    __shared__ const float* s_ptr[NENT][4];  // base + corner offset, precomputed
    __shared__ int   s_HW[NENT];
    __shared__ float s_w[NENT][4];
    __shared__ int   s_list[NENT];
    __shared__ int   s_ne;
    __shared__ float s_cnt;

    // ---- Phase 1 (warp 0 only): build entries + ballot compaction ----
    if (wrp == 0) {
        const int t   = L;               // entry index (t<24 meaningful)
        const int n   = t >> 2;          // camera
        const int lvl = t & 3;           // level

        int  active = 0;
        bool vcam   = false;

        if (t < NENT) {
            const float* rp = refpts + (size_t)bm * 3;
            float rx = rp[0] * 122.4f - 61.2f;
            float ry = rp[1] * 122.4f - 61.2f;
            float rz = rp[2] * 20.0f  - 10.0f;

            const float* Mt = l2i + (size_t)(b * NCAM + n) * 16;
            float cx = Mt[0]*rx + Mt[1]*ry + Mt[2] *rz + Mt[3];
            float cy = Mt[4]*rx + Mt[5]*ry + Mt[6] *rz + Mt[7];
            float cz = Mt[8]*rx + Mt[9]*ry + Mt[10]*rz + Mt[11];

            vcam = (cz > EPSV);

            float inv = 1.0f / (cz + EPSV);
            float x = cx * inv - 0.5f;   // grid_sample denorm cancels across levels
            float y = cy * inv - 0.5f;

            const int W  = c_W[lvl];
            const int H  = c_H[lvl];
            const int HW = c_HW[lvl];

            if (vcam && (x > -1.0f) && (x < (float)W) && (y > -1.0f) && (y < (float)H)) {
                float x0f = floorf(x), y0f = floorf(y);
                float wx1 = x - x0f, wx0 = 1.0f - wx1;
                float wy1 = y - y0f, wy0 = 1.0f - wy1;

                bool vx0 = (x0f >= 0.0f)        && (x0f <= (float)(W - 1));
                bool vx1 = (x0f + 1.0f >= 0.0f) && (x0f + 1.0f <= (float)(W - 1));
                bool vy0 = (y0f >= 0.0f)        && (y0f <= (float)(H - 1));
                bool vy1 = (y0f + 1.0f >= 0.0f) && (y0f + 1.0f <= (float)(H - 1));

                int xi0 = (int)fminf(fmaxf(x0f,        0.0f), (float)(W - 1));
                int xi1 = (int)fminf(fmaxf(x0f + 1.0f, 0.0f), (float)(W - 1));
                int yi0 = (int)fminf(fmaxf(y0f,        0.0f), (float)(H - 1));
                int yi1 = (int)fminf(fmaxf(y0f + 1.0f, 0.0f), (float)(H - 1));

                float w00 = (vx0 && vy0) ? (wx0 * wy0) : 0.0f;
                float w01 = (vx1 && vy0) ? (wx1 * wy0) : 0.0f;
                float w10 = (vx0 && vy1) ? (wx0 * wy1) : 0.0f;
                float w11 = (vx1 && vy1) ? (wx1 * wy1) : 0.0f;

                if ((w00 != 0.0f) || (w01 != 0.0f) || (w10 != 0.0f) || (w11 != 0.0f)) {
                    active = 1;
                    const float* fl = (lvl == 0) ? f0 : (lvl == 1) ? f1 :
                                      (lvl == 2) ? f2 : f3;
                    const float* base = fl + (size_t)(b * NCAM + n) * CCH * HW;
                    s_HW[t]     = HW;
                    s_ptr[t][0] = base + (yi0 * W + xi0);
                    s_ptr[t][1] = base + (yi0 * W + xi1);
                    s_ptr[t][2] = base + (yi1 * W + xi0);
                    s_ptr[t][3] = base + (yi1 * W + xi1);
                    s_w[t][0] = w00;  s_w[t][1] = w01;
                    s_w[t][2] = w10;  s_w[t][3] = w11;
                }
            }
        }

        // ballot compaction: O(1)
        unsigned amask = __ballot_sync(0xFFFFFFFFu, active != 0);
        if (active) {
            int pos = __popc(amask & ((1u << t) - 1u));
            s_list[pos] = t;
        }
        unsigned vmask = __ballot_sync(0xFFFFFFFFu, vcam && (lvl == 0) && (t < NENT));
        if (L == 0) {
            s_ne  = __popc(amask);
            s_cnt = (float)__popc(vmask);
        }
    }
    __syncthreads();

    const int   ne  = s_ne;
    const float cnt = s_cnt;

    // ---- Phase 2: per-lane weighted accumulation (x2 unroll, 8 LDGs/iter) ----
    float acc0 = 0.0f, acc1 = 0.0f, acc2 = 0.0f, acc3 = 0.0f;

    int k = 0;
    for (; k + 1 < ne; k += 2) {
        const int ea = s_list[k];
        const int eb = s_list[k + 1];
        const int HWa = s_HW[ea];
        const int HWb = s_HW[eb];
        const float wa = s_w[ea][corner];
        const float wb = s_w[eb][corner];
        const float* pa = s_ptr[ea][corner] + (size_t)chsub * HWa;
        const float* pb = s_ptr[eb][corner] + (size_t)chsub * HWb;

        float a0 = __ldg(pa);
        float a1 = __ldg(pa + (size_t)64  * HWa);
        float a2 = __ldg(pa + (size_t)128 * HWa);
        float a3 = __ldg(pa + (size_t)192 * HWa);
        float b0 = __ldg(pb);
        float b1 = __ldg(pb + (size_t)64  * HWb);
        float b2 = __ldg(pb + (size_t)128 * HWb);
        float b3 = __ldg(pb + (size_t)192 * HWb);

        acc0 += a0 * wa;  acc1 += a1 * wa;
        acc2 += a2 * wa;  acc3 += a3 * wa;
        acc0 += b0 * wb;  acc1 += b1 * wb;
        acc2 += b2 * wb;  acc3 += b3 * wb;
    }
    if (k < ne) {
        const int ea = s_list[k];
        const int HWa = s_HW[ea];
        const float wa = s_w[ea][corner];
        const float* pa = s_ptr[ea][corner] + (size_t)chsub * HWa;
        acc0 += __ldg(pa)                     * wa;
        acc1 += __ldg(pa + (size_t)64  * HWa) * wa;
        acc2 += __ldg(pa + (size_t)128 * HWa) * wa;
        acc3 += __ldg(pa + (size_t)192 * HWa) * wa;
    }

    // single quad butterfly at the end (sum the 4 corners)
    acc0 += __shfl_xor_sync(0xFFFFFFFFu, acc0, 1);
    acc1 += __shfl_xor_sync(0xFFFFFFFFu, acc1, 1);
    acc2 += __shfl_xor_sync(0xFFFFFFFFu, acc2, 1);
    acc3 += __shfl_xor_sync(0xFFFFFFFFu, acc3, 1);
    acc0 += __shfl_xor_sync(0xFFFFFFFFu, acc0, 2);
    acc1 += __shfl_xor_sync(0xFFFFFFFFu, acc1, 2);
    acc2 += __shfl_xor_sync(0xFFFFFFFFu, acc2, 2);
    acc3 += __shfl_xor_sync(0xFFFFFFFFu, acc3, 2);

    if (corner == 0) {
        const float s = 0.25f / (cnt + EPSV);
        float* o = out + (size_t)bm * CCH + chsub;
        o[0]   = acc0 * s;
        o[64]  = acc1 * s;
        o[128] = acc2 * s;
        o[192] = acc3 * s;
    }
}

extern "C" void kernel_launch(void* const* d_in, const int* in_sizes, int n_in,
                              void* d_out, int out_size)
{
    const float* f0  = (const float*)d_in[0];
    const float* f1  = (const float*)d_in[1];
    const float* f2  = (const float*)d_in[2];
    const float* f3  = (const float*)d_in[3];
    const float* rp  = (const float*)d_in[4];
    const float* l2i = (const float*)d_in[5];
    float* out = (float*)d_out;

    dim3 grid(BQ * MQ, 2);
    dim3 block(128);
    FeatureSampler_kernel<<<grid, block>>>(f0, f1, f2, f3, rp, l2i, out);
}